// round 9
// baseline (speedup 1.0000x reference)
#include <cuda_runtime.h>
#include <cstdint>

// Problem constants
// B=32, L=512, E=H=512, G=4H=2048, N=2 layers, V=32000
#define NB 32
#define NL 512
#define NH 512
#define NG 2048
#define NLAYERS 2

// Scratch (static device globals -- allocation-free)
__device__ float g_xg[(size_t)NL * NB * NG];      // (L*B, 4H) gate preactivations (input part + bias)
__device__ float g_hseq[(size_t)NL * NB * NH];    // (L*B, H) layer-0 output sequence
__device__ float g_hstate[2 * NH * NB];           // double-buffered h, layout [buf][k][b]
__device__ int   g_bar;                           // global barrier counter

// ---------------------------------------------------------------------------
// init: zero h state + barrier counter
// ---------------------------------------------------------------------------
__global__ void init_kernel() {
    int tid = threadIdx.x;
    for (int i = tid; i < 2 * NH * NB; i += 256) g_hstate[i] = 0.f;
    if (tid == 0) g_bar = 0;
}

// ---------------------------------------------------------------------------
// xg GEMM: xg[m][n] = sum_k A[m][k] * W[n][k] + (bih[n]+bhh[n])
//   m = t*32 + b  (M = 16384), n in [0,2048), K = 512
//   gather=1: A row = emb[tokens[b*512+t]]; gather=0: A row = g_hseq[m]
// 128x128x8 tile, 256 threads, 8x8 microtile.
// ---------------------------------------------------------------------------
__global__ __launch_bounds__(256) void xg_gemm(
    const float* __restrict__ emb,
    const int*   __restrict__ tokens,
    int gather,
    const float* __restrict__ W,        // (2048, 512) row-major
    const float* __restrict__ bih_l,
    const float* __restrict__ bhh_l)
{
    __shared__ float As[8][128];
    __shared__ float Bs[8][128];
    __shared__ float bias_s[128];

    const int tid = threadIdx.x;
    const int n0 = blockIdx.x * 128;
    const int m0 = blockIdx.y * 128;

    if (tid < 128) bias_s[tid] = bih_l[n0 + tid] + bhh_l[n0 + tid];

    const int lr = tid >> 1;          // 0..127 tile row for loading
    const int kq = (tid & 1) * 4;     // 0 or 4

    const float* arow;
    {
        int m = m0 + lr;
        if (gather) {
            int t = m >> 5, b = m & 31;
            int tok = tokens[b * NL + t];
            arow = emb + (size_t)tok * 512;
        } else {
            arow = g_hseq + (size_t)m * 512;
        }
    }
    const float* brow = W + (size_t)(n0 + lr) * 512;

    const int tm = (tid >> 4) * 8;
    const int tn = (tid & 15) * 8;

    float acc[8][8];
#pragma unroll
    for (int i = 0; i < 8; i++)
#pragma unroll
        for (int j = 0; j < 8; j++) acc[i][j] = 0.f;

    for (int k0 = 0; k0 < 512; k0 += 8) {
        float4 av = *(const float4*)(arow + k0 + kq);
        float4 bv = *(const float4*)(brow + k0 + kq);
        __syncthreads();
        As[kq + 0][lr] = av.x; As[kq + 1][lr] = av.y;
        As[kq + 2][lr] = av.z; As[kq + 3][lr] = av.w;
        Bs[kq + 0][lr] = bv.x; Bs[kq + 1][lr] = bv.y;
        Bs[kq + 2][lr] = bv.z; Bs[kq + 3][lr] = bv.w;
        __syncthreads();
#pragma unroll
        for (int kk = 0; kk < 8; kk++) {
            float a[8], b[8];
            *(float4*)(a)     = *(const float4*)(&As[kk][tm]);
            *(float4*)(a + 4) = *(const float4*)(&As[kk][tm + 4]);
            *(float4*)(b)     = *(const float4*)(&Bs[kk][tn]);
            *(float4*)(b + 4) = *(const float4*)(&Bs[kk][tn + 4]);
#pragma unroll
            for (int i = 0; i < 8; i++)
#pragma unroll
                for (int j = 0; j < 8; j++)
                    acc[i][j] += a[i] * b[j];
        }
    }

#pragma unroll
    for (int i = 0; i < 8; i++) {
        float* orow = g_xg + (size_t)(m0 + tm + i) * NG + n0 + tn;
        float4 v0 = make_float4(acc[i][0] + bias_s[tn + 0], acc[i][1] + bias_s[tn + 1],
                                acc[i][2] + bias_s[tn + 2], acc[i][3] + bias_s[tn + 3]);
        float4 v1 = make_float4(acc[i][4] + bias_s[tn + 4], acc[i][5] + bias_s[tn + 5],
                                acc[i][6] + bias_s[tn + 6], acc[i][7] + bias_s[tn + 7]);
        *(float4*)(orow)     = v0;
        *(float4*)(orow + 4) = v1;
    }
}

// ---------------------------------------------------------------------------
// Persistent LSTM recurrence: 128 CTAs x 256 threads, one CTA per 4 hidden
// units (16 gate rows). Weights resident in smem for all 512 steps.
// Per step: stage h (k-major [k][b]) to smem, warps split K (8 x 64),
// 4x4 register tile per lane, smem reduction, fused gates, global spin
// barrier with double-buffered h state.
// ---------------------------------------------------------------------------
__global__ __launch_bounds__(256, 1) void lstm_rec(
    const float* __restrict__ Whh_l,   // (2048, 512)
    int write_seq, int layer,
    float* __restrict__ d_out)
{
    extern __shared__ float sm[];
    float* hs   = sm;                    // 512*32  = 16384 floats  (h, [k][b])
    float* w_s  = hs  + 512 * 32;        // 512*16  = 8192          (Whh^T slice, [k][lr])
    float* red  = w_s + 512 * 16;        // 8*16*32 = 4096          (per-warp partials)
    float* gate = red + 8 * 16 * 32;     // 16*32   = 512
    float* c_s  = gate + 16 * 32;        // 4*32    = 128           (cell state, persistent)

    const int tid = threadIdx.x;
    const int cta = blockIdx.x;          // 0..127 -> units [cta*4, cta*4+4)

    // One-time: load 16 gate rows of Whh, transposed into [k][lr]
    for (int idx = tid; idx < 16 * 512; idx += 256) {
        int lrw = idx >> 9;              // 0..15
        int k   = idx & 511;
        int q = lrw >> 2, u = lrw & 3;
        int row = q * 512 + cta * 4 + u;
        w_s[k * 16 + lrw] = Whh_l[(size_t)row * 512 + k];
    }
    if (tid < 128) c_s[tid] = 0.f;
    __syncthreads();

    const int lane = tid & 31, warp = tid >> 5;
    const int rg = lane >> 3, bg = lane & 7;
    const int k0 = warp * 64;

    // Reduce-phase output assignment (2 per thread)
    const int o0 = tid, o1 = tid + 256;
    const int lr0 = o0 >> 5, b0 = o0 & 31;
    const int lr1 = o1 >> 5, b1 = o1 & 31;
    const int row0 = (lr0 >> 2) * 512 + cta * 4 + (lr0 & 3);
    const int row1 = (lr1 >> 2) * 512 + cta * 4 + (lr1 & 3);

    for (int t = 0; t < NL; t++) {
        // Prefetch xg for this step (independent of h -> overlaps dot products)
        float xg0 = __ldg(g_xg + (size_t)(t * 32 + b0) * NG + row0);
        float xg1 = __ldg(g_xg + (size_t)(t * 32 + b1) * NG + row1);

        // Stage h_{t-1} into smem
        const float* hsrc = g_hstate + (t & 1) * NH * NB;
        for (int i = tid * 4; i < 512 * 32; i += 256 * 4)
            *(float4*)(hs + i) = *(const float4*)(hsrc + i);
        __syncthreads();

        // Dot products: this warp handles K in [k0, k0+64)
        float acc[4][4];
#pragma unroll
        for (int i = 0; i < 4; i++)
#pragma unroll
            for (int j = 0; j < 4; j++) acc[i][j] = 0.f;

#pragma unroll 4
        for (int k = k0; k < k0 + 64; k++) {
            float4 wv = *(const float4*)(w_s + k * 16 + rg * 4);
            float4 hv = *(const float4*)(hs  + k * 32 + bg * 4);
            acc[0][0] += wv.x * hv.x; acc[0][1] += wv.x * hv.y;
            acc[0][2] += wv.x * hv.z; acc[0][3] += wv.x * hv.w;
            acc[1][0] += wv.y * hv.x; acc[1][1] += wv.y * hv.y;
            acc[1][2] += wv.y * hv.z; acc[1][3] += wv.y * hv.w;
            acc[2][0] += wv.z * hv.x; acc[2][1] += wv.z * hv.y;
            acc[2][2] += wv.z * hv.z; acc[2][3] += wv.z * hv.w;
            acc[3][0] += wv.w * hv.x; acc[3][1] += wv.w * hv.y;
            acc[3][2] += wv.w * hv.z; acc[3][3] += wv.w * hv.w;
        }
#pragma unroll
        for (int ri = 0; ri < 4; ri++)
            *(float4*)(red + ((warp * 16 + rg * 4 + ri) * 32 + bg * 4)) =
                make_float4(acc[ri][0], acc[ri][1], acc[ri][2], acc[ri][3]);
        __syncthreads();

        // Cross-warp K reduction + add xg (bias already in xg)
        {
            float s0 = xg0, s1 = xg1;
#pragma unroll
            for (int w = 0; w < 8; w++) {
                s0 += red[(w * 16 + lr0) * 32 + b0];
                s1 += red[(w * 16 + lr1) * 32 + b1];
            }
            gate[lr0 * 32 + b0] = s0;
            gate[lr1 * 32 + b1] = s1;
        }
        __syncthreads();

        // Gates + state update (torch order i, f, g, o; lr = q*4 + u)
        if (tid < 128) {
            int u = tid >> 5, b = tid & 31;
            float gi = gate[(0 + u) * 32 + b];
            float gf = gate[(4 + u) * 32 + b];
            float gg = gate[(8 + u) * 32 + b];
            float go = gate[(12 + u) * 32 + b];
            float ig = 1.f / (1.f + __expf(-gi));
            float fg = 1.f / (1.f + __expf(-gf));
            float cg = tanhf(gg);
            float og = 1.f / (1.f + __expf(-go));
            float c = fg * c_s[tid] + ig * cg;
            c_s[tid] = c;
            float h = og * tanhf(c);
            int j = cta * 4 + u;
            g_hstate[((t + 1) & 1) * NH * NB + j * 32 + b] = h;
            if (write_seq) g_hseq[(size_t)(t * 32 + b) * NH + j] = h;
            if (t == NL - 1) {
                d_out[layer * NB * NH + b * NH + j] = h;                       // hidden
                d_out[NLAYERS * NB * NH + layer * NB * NH + b * NH + j] = c;   // cell
            }
        }
        __syncthreads();

        // Grid-wide barrier (release-acquire via fence + monotonic counter)
        if (tid == 0) {
            __threadfence();
            atomicAdd(&g_bar, 1);
            int target = 128 * (t + 1);
            int v;
            do {
                asm volatile("ld.acquire.gpu.s32 %0, [%1];" : "=r"(v) : "l"(&g_bar));
            } while (v < target);
        }
        __syncthreads();
    }
}

// ---------------------------------------------------------------------------
// Launcher
// ---------------------------------------------------------------------------
extern "C" void kernel_launch(void* const* d_in, const int* in_sizes, int n_in,
                              void* d_out, int out_size) {
    const int*   tokens = (const int*)  d_in[0];
    const float* emb    = (const float*)d_in[1];
    const float* Wih    = (const float*)d_in[2];   // (2, 2048, 512)
    const float* Whh    = (const float*)d_in[3];   // (2, 2048, 512)
    const float* bih    = (const float*)d_in[4];   // (2, 2048)
    const float* bhh    = (const float*)d_in[5];   // (2, 2048)
    float* out = (float*)d_out;

    const int REC_SMEM = (512 * 32 + 512 * 16 + 8 * 16 * 32 + 16 * 32 + 4 * 32) * 4;
    cudaFuncSetAttribute(lstm_rec, cudaFuncAttributeMaxDynamicSharedMemorySize, REC_SMEM);

    dim3 ggrid(NG / 128, (NL * NB) / 128);   // (16, 128)

    // ---- layer 0 ----
    xg_gemm<<<ggrid, 256>>>(emb, tokens, 1, Wih, bih, bhh);
    init_kernel<<<1, 256>>>();
    lstm_rec<<<128, 256, REC_SMEM>>>(Whh, 1, 0, out);

    // ---- layer 1 ----
    xg_gemm<<<ggrid, 256>>>(emb, tokens, 0, Wih + (size_t)NG * NH, bih + NG, bhh + NG);
    init_kernel<<<1, 256>>>();
    lstm_rec<<<128, 256, REC_SMEM>>>(Whh + (size_t)NG * NH, 0, 1, out);
}

// round 10
// speedup vs baseline: 1.2163x; 1.2163x over previous
#include <cuda_runtime.h>
#include <cstdint>

// Problem constants
// B=32, L=512, E=H=512, G=4H=2048, N=2 layers, V=32000
#define NB 32
#define NL 512
#define NH 512
#define NG 2048
#define NLAYERS 2

// Scratch (static device globals -- allocation-free)
__device__ float g_xg[(size_t)NL * NB * NG];      // (L*B, 4H) gate preactivations (input part + bias)
__device__ float g_hseq[(size_t)NL * NB * NH];    // (L*B, H) layer-0 output sequence
__device__ float g_hstate[2 * NH * NB];           // double-buffered h, layout [buf][k][b]
__device__ int   g_bar;                           // global barrier counter

// ---------------------------------------------------------------------------
// Packed f32x2 helpers (FFMA2 -- 2 fp32 MACs per instruction; ptxas never
// emits this from C++, only reachable via PTX fma.rn.f32x2)
// ---------------------------------------------------------------------------
__device__ __forceinline__ unsigned long long ffma2(unsigned long long a,
                                                    unsigned long long b,
                                                    unsigned long long c) {
    unsigned long long d;
    asm("fma.rn.f32x2 %0, %1, %2, %3;" : "=l"(d) : "l"(a), "l"(b), "l"(c));
    return d;
}
__device__ __forceinline__ unsigned long long addf2(unsigned long long a,
                                                    unsigned long long b) {
    unsigned long long d;
    asm("add.rn.f32x2 %0, %1, %2;" : "=l"(d) : "l"(a), "l"(b));
    return d;
}
__device__ __forceinline__ unsigned long long pack2(float x) {
    unsigned long long d;
    asm("mov.b64 %0, {%1, %1};" : "=l"(d) : "f"(x));
    return d;
}
__device__ __forceinline__ float2 unpack2(unsigned long long u) {
    float2 f;
    asm("mov.b64 {%0, %1}, %2;" : "=f"(f.x), "=f"(f.y) : "l"(u));
    return f;
}

// ---------------------------------------------------------------------------
// init: zero h state + barrier counter
// ---------------------------------------------------------------------------
__global__ void init_kernel() {
    int tid = threadIdx.x;
    for (int i = tid; i < 2 * NH * NB; i += 256) g_hstate[i] = 0.f;
    if (tid == 0) g_bar = 0;
}

// ---------------------------------------------------------------------------
// xg GEMM: xg[m][n] = sum_k A[m][k] * W[n][k] + (bih[n]+bhh[n])
// 128x128x8 tile, 256 threads, 8x8 microtile, FFMA2 inner product.
// ---------------------------------------------------------------------------
__global__ __launch_bounds__(256) void xg_gemm(
    const float* __restrict__ emb,
    const int*   __restrict__ tokens,
    int gather,
    const float* __restrict__ W,        // (2048, 512) row-major
    const float* __restrict__ bih_l,
    const float* __restrict__ bhh_l)
{
    __shared__ float As[8][128];
    __shared__ float Bs[8][128];
    __shared__ float bias_s[128];

    const int tid = threadIdx.x;
    const int n0 = blockIdx.x * 128;
    const int m0 = blockIdx.y * 128;

    if (tid < 128) bias_s[tid] = bih_l[n0 + tid] + bhh_l[n0 + tid];

    const int lr = tid >> 1;          // 0..127 tile row for loading
    const int kq = (tid & 1) * 4;     // 0 or 4

    const float* arow;
    {
        int m = m0 + lr;
        if (gather) {
            int t = m >> 5, b = m & 31;
            int tok = tokens[b * NL + t];
            arow = emb + (size_t)tok * 512;
        } else {
            arow = g_hseq + (size_t)m * 512;
        }
    }
    const float* brow = W + (size_t)(n0 + lr) * 512;

    const int tm = (tid >> 4) * 8;
    const int tn = (tid & 15) * 8;

    unsigned long long acc2[8][4];    // 8 rows x 4 f32x2 pairs (8 cols)
#pragma unroll
    for (int i = 0; i < 8; i++)
#pragma unroll
        for (int p = 0; p < 4; p++) acc2[i][p] = 0ull;

    for (int k0 = 0; k0 < 512; k0 += 8) {
        float4 av = *(const float4*)(arow + k0 + kq);
        float4 bv = *(const float4*)(brow + k0 + kq);
        __syncthreads();
        As[kq + 0][lr] = av.x; As[kq + 1][lr] = av.y;
        As[kq + 2][lr] = av.z; As[kq + 3][lr] = av.w;
        Bs[kq + 0][lr] = bv.x; Bs[kq + 1][lr] = bv.y;
        Bs[kq + 2][lr] = bv.z; Bs[kq + 3][lr] = bv.w;
        __syncthreads();
#pragma unroll
        for (int kk = 0; kk < 8; kk++) {
            float a[8];
            *(float4*)(a)     = *(const float4*)(&As[kk][tm]);
            *(float4*)(a + 4) = *(const float4*)(&As[kk][tm + 4]);
            ulonglong2 b01 = *(const ulonglong2*)(&Bs[kk][tn]);
            ulonglong2 b23 = *(const ulonglong2*)(&Bs[kk][tn + 4]);
#pragma unroll
            for (int i = 0; i < 8; i++) {
                unsigned long long ad = pack2(a[i]);
                acc2[i][0] = ffma2(ad, b01.x, acc2[i][0]);
                acc2[i][1] = ffma2(ad, b01.y, acc2[i][1]);
                acc2[i][2] = ffma2(ad, b23.x, acc2[i][2]);
                acc2[i][3] = ffma2(ad, b23.y, acc2[i][3]);
            }
        }
    }

    ulonglong2 bi01 = *(const ulonglong2*)(&bias_s[tn]);
    ulonglong2 bi23 = *(const ulonglong2*)(&bias_s[tn + 4]);
#pragma unroll
    for (int i = 0; i < 8; i++) {
        float* orow = g_xg + (size_t)(m0 + tm + i) * NG + n0 + tn;
        ulonglong2 o0, o1;
        o0.x = addf2(acc2[i][0], bi01.x);
        o0.y = addf2(acc2[i][1], bi01.y);
        o1.x = addf2(acc2[i][2], bi23.x);
        o1.y = addf2(acc2[i][3], bi23.y);
        *(ulonglong2*)(orow)     = o0;
        *(ulonglong2*)(orow + 4) = o1;
    }
}

// ---------------------------------------------------------------------------
// Persistent LSTM recurrence: 128 CTAs x 256 threads, one CTA per 4 hidden
// units (16 gate rows). Whh slice resident in smem PRE-DUPLICATED as (w,w)
// pairs so the inner product runs on fma.rn.f32x2 (2 MACs/inst).
// Per step: each warp stages its OWN 8KB K-slice of h (syncwarp only), then
// 3 LDS.128 + 8 FFMA2 per k, smem reduction, fused gates, global barrier.
// ---------------------------------------------------------------------------
__global__ __launch_bounds__(256, 1) void lstm_rec(
    const float* __restrict__ Whh_l,   // (2048, 512)
    int write_seq, int layer,
    float* __restrict__ d_out)
{
    extern __shared__ float sm[];
    float* hs   = sm;                    // 512*32  = 16384 floats  (h, [k][b])
    float* w2_s = hs  + 512 * 32;        // 512*32  = 16384         (Whh^T slice, [k][lr] duplicated pairs)
    float* red  = w2_s + 512 * 32;       // 8*16*32 = 4096          (per-warp partials)
    float* gate = red + 8 * 16 * 32;     // 16*32   = 512
    float* c_s  = gate + 16 * 32;        // 4*32    = 128           (cell state, persistent)

    const int tid = threadIdx.x;
    const int cta = blockIdx.x;          // 0..127 -> units [cta*4, cta*4+4)

    // One-time: load 16 gate rows of Whh, transposed + duplicated into [k][2*lr]
    for (int idx = tid; idx < 16 * 512; idx += 256) {
        int lrw = idx >> 9;              // 0..15
        int k   = idx & 511;
        int q = lrw >> 2, u = lrw & 3;
        int row = q * 512 + cta * 4 + u;
        float w = Whh_l[(size_t)row * 512 + k];
        w2_s[k * 32 + lrw * 2]     = w;
        w2_s[k * 32 + lrw * 2 + 1] = w;
    }
    if (tid < 128) c_s[tid] = 0.f;
    __syncthreads();

    const int lane = tid & 31, warp = tid >> 5;
    const int rg = lane >> 3, bg = lane & 7;
    const int k0 = warp * 64;

    // Reduce-phase output assignment (2 per thread)
    const int o0 = tid, o1 = tid + 256;
    const int lr0 = o0 >> 5, b0 = o0 & 31;
    const int lr1 = o1 >> 5, b1 = o1 & 31;
    const int row0 = (lr0 >> 2) * 512 + cta * 4 + (lr0 & 3);
    const int row1 = (lr1 >> 2) * 512 + cta * 4 + (lr1 & 3);

    const float* wbase = w2_s + rg * 8;
    const float* hbase = hs + bg * 4;

    for (int t = 0; t < NL; t++) {
        // Prefetch xg for this step (independent of h -> overlaps everything)
        float xg0 = __ldg(g_xg + (size_t)(t * 32 + b0) * NG + row0);
        float xg1 = __ldg(g_xg + (size_t)(t * 32 + b1) * NG + row1);

        // Per-warp staging: warp w stages h rows [k0, k0+64) -- its own slice only
        {
            const float* src = g_hstate + (t & 1) * NH * NB + k0 * 32;
            float* dst = hs + k0 * 32;
#pragma unroll
            for (int i = 0; i < 16; i++) {
                int off = lane * 4 + i * 128;
                *(float4*)(dst + off) = *(const float4*)(src + off);
            }
            __syncwarp();
        }

        // Dot products: this warp handles K in [k0, k0+64), FFMA2 microtile
        unsigned long long a00 = 0, a01 = 0, a10 = 0, a11 = 0;
        unsigned long long a20 = 0, a21 = 0, a30 = 0, a31 = 0;
#pragma unroll 4
        for (int k = k0; k < k0 + 64; k++) {
            ulonglong2 W01 = *(const ulonglong2*)(wbase + k * 32);
            ulonglong2 W23 = *(const ulonglong2*)(wbase + k * 32 + 4);
            ulonglong2 H   = *(const ulonglong2*)(hbase + k * 32);
            a00 = ffma2(W01.x, H.x, a00); a01 = ffma2(W01.x, H.y, a01);
            a10 = ffma2(W01.y, H.x, a10); a11 = ffma2(W01.y, H.y, a11);
            a20 = ffma2(W23.x, H.x, a20); a21 = ffma2(W23.x, H.y, a21);
            a30 = ffma2(W23.y, H.x, a30); a31 = ffma2(W23.y, H.y, a31);
        }
        {
            float2 p, q;
            p = unpack2(a00); q = unpack2(a01);
            *(float4*)(red + ((warp * 16 + rg * 4 + 0) * 32 + bg * 4)) = make_float4(p.x, p.y, q.x, q.y);
            p = unpack2(a10); q = unpack2(a11);
            *(float4*)(red + ((warp * 16 + rg * 4 + 1) * 32 + bg * 4)) = make_float4(p.x, p.y, q.x, q.y);
            p = unpack2(a20); q = unpack2(a21);
            *(float4*)(red + ((warp * 16 + rg * 4 + 2) * 32 + bg * 4)) = make_float4(p.x, p.y, q.x, q.y);
            p = unpack2(a30); q = unpack2(a31);
            *(float4*)(red + ((warp * 16 + rg * 4 + 3) * 32 + bg * 4)) = make_float4(p.x, p.y, q.x, q.y);
        }
        __syncthreads();

        // Cross-warp K reduction + add xg (bias already in xg)
        {
            float s0 = xg0, s1 = xg1;
#pragma unroll
            for (int w = 0; w < 8; w++) {
                s0 += red[(w * 16 + lr0) * 32 + b0];
                s1 += red[(w * 16 + lr1) * 32 + b1];
            }
            gate[lr0 * 32 + b0] = s0;
            gate[lr1 * 32 + b1] = s1;
        }
        __syncthreads();

        // Gates + state update (torch order i, f, g, o; lr = q*4 + u)
        if (tid < 128) {
            int u = tid >> 5, b = tid & 31;
            float gi = gate[(0 + u) * 32 + b];
            float gf = gate[(4 + u) * 32 + b];
            float gg = gate[(8 + u) * 32 + b];
            float go = gate[(12 + u) * 32 + b];
            float ig = 1.f / (1.f + __expf(-gi));
            float fg = 1.f / (1.f + __expf(-gf));
            float cg = tanhf(gg);
            float og = 1.f / (1.f + __expf(-go));
            float c = fg * c_s[tid] + ig * cg;
            c_s[tid] = c;
            float h = og * tanhf(c);
            int j = cta * 4 + u;
            g_hstate[((t + 1) & 1) * NH * NB + j * 32 + b] = h;
            if (write_seq) g_hseq[(size_t)(t * 32 + b) * NH + j] = h;
            if (t == NL - 1) {
                d_out[layer * NB * NH + b * NH + j] = h;                       // hidden
                d_out[NLAYERS * NB * NH + layer * NB * NH + b * NH + j] = c;   // cell
            }
        }
        __syncthreads();

        // Grid-wide barrier (release-acquire via fence + monotonic counter)
        if (tid == 0) {
            __threadfence();
            atomicAdd(&g_bar, 1);
            int target = 128 * (t + 1);
            int v;
            do {
                asm volatile("ld.acquire.gpu.s32 %0, [%1];" : "=r"(v) : "l"(&g_bar));
            } while (v < target);
        }
        __syncthreads();
    }
}

// ---------------------------------------------------------------------------
// Launcher
// ---------------------------------------------------------------------------
extern "C" void kernel_launch(void* const* d_in, const int* in_sizes, int n_in,
                              void* d_out, int out_size) {
    const int*   tokens = (const int*)  d_in[0];
    const float* emb    = (const float*)d_in[1];
    const float* Wih    = (const float*)d_in[2];   // (2, 2048, 512)
    const float* Whh    = (const float*)d_in[3];   // (2, 2048, 512)
    const float* bih    = (const float*)d_in[4];   // (2, 2048)
    const float* bhh    = (const float*)d_in[5];   // (2, 2048)
    float* out = (float*)d_out;

    const int REC_SMEM = (512 * 32 + 512 * 32 + 8 * 16 * 32 + 16 * 32 + 4 * 32) * 4;
    cudaFuncSetAttribute(lstm_rec, cudaFuncAttributeMaxDynamicSharedMemorySize, REC_SMEM);

    dim3 ggrid(NG / 128, (NL * NB) / 128);   // (16, 128)

    // ---- layer 0 ----
    xg_gemm<<<ggrid, 256>>>(emb, tokens, 1, Wih, bih, bhh);
    init_kernel<<<1, 256>>>();
    lstm_rec<<<128, 256, REC_SMEM>>>(Whh, 1, 0, out);

    // ---- layer 1 ----
    xg_gemm<<<ggrid, 256>>>(emb, tokens, 0, Wih + (size_t)NG * NH, bih + NG, bhh + NG);
    init_kernel<<<1, 256>>>();
    lstm_rec<<<128, 256, REC_SMEM>>>(Whh + (size_t)NG * NH, 0, 1, out);
}

// round 11
// speedup vs baseline: 1.2556x; 1.0324x over previous
#include <cuda_runtime.h>
#include <cstdint>

// Problem constants
// B=32, L=512, E=H=512, G=4H=2048, N=2 layers, V=32000
#define NB 32
#define NL 512
#define NH 512
#define NG 2048
#define NLAYERS 2

// Scratch (static device globals -- allocation-free)
__device__ float g_xg[(size_t)NL * NB * NG];   // (L*B, 4H) layer-0 gate preacts (input part + bias)
__device__ float g_h0[2 * NH * NB];            // double-buffered h layer0, [buf][j][b]
__device__ float g_h1[2 * NH * NB];            // double-buffered h layer1, [buf][j][b]
__device__ int   g_bar;                        // global barrier counter

// ---------------------------------------------------------------------------
// Packed f32x2 helpers (fma.rn.f32x2 -- 2 fp32 MACs per instruction)
// ---------------------------------------------------------------------------
__device__ __forceinline__ unsigned long long ffma2(unsigned long long a,
                                                    unsigned long long b,
                                                    unsigned long long c) {
    unsigned long long d;
    asm("fma.rn.f32x2 %0, %1, %2, %3;" : "=l"(d) : "l"(a), "l"(b), "l"(c));
    return d;
}
__device__ __forceinline__ unsigned long long addf2(unsigned long long a,
                                                    unsigned long long b) {
    unsigned long long d;
    asm("add.rn.f32x2 %0, %1, %2;" : "=l"(d) : "l"(a), "l"(b));
    return d;
}
__device__ __forceinline__ unsigned long long pack2(float x) {
    unsigned long long d;
    asm("mov.b64 %0, {%1, %1};" : "=l"(d) : "f"(x));
    return d;
}
__device__ __forceinline__ float2 unpack2(unsigned long long u) {
    float2 f;
    asm("mov.b64 {%0, %1}, %2;" : "=f"(f.x), "=f"(f.y) : "l"(u));
    return f;
}

__device__ __forceinline__ float sigm_f(float x) {
    return 1.f / (1.f + __expf(-x));
}
// tanh via exp, precise division; clamp avoids inf/inf NaN. err ~1e-6 rel.
__device__ __forceinline__ float tanh_f(float x) {
    float xx = fminf(fmaxf(x, -15.f), 15.f);
    float e = __expf(2.f * xx);
    return (e - 1.f) / (e + 1.f);
}

// ---------------------------------------------------------------------------
// init: zero h states + barrier counter
// ---------------------------------------------------------------------------
__global__ void init_kernel() {
    int tid = threadIdx.x;
    for (int i = tid; i < 2 * NH * NB; i += 256) { g_h0[i] = 0.f; g_h1[i] = 0.f; }
    if (tid == 0) g_bar = 0;
}

// ---------------------------------------------------------------------------
// xg GEMM (layer 0 only): xg[m][n] = emb[tokens] @ Wih0^T + (bih0+bhh0)
// 128x128x8 tile, 256 threads, 8x8 microtile, FFMA2 inner product.
// ---------------------------------------------------------------------------
__global__ __launch_bounds__(256) void xg_gemm(
    const float* __restrict__ emb,
    const int*   __restrict__ tokens,
    const float* __restrict__ W,        // (2048, 512) row-major
    const float* __restrict__ bih_l,
    const float* __restrict__ bhh_l)
{
    __shared__ float As[8][128];
    __shared__ float Bs[8][128];
    __shared__ float bias_s[128];

    const int tid = threadIdx.x;
    const int n0 = blockIdx.x * 128;
    const int m0 = blockIdx.y * 128;

    if (tid < 128) bias_s[tid] = bih_l[n0 + tid] + bhh_l[n0 + tid];

    const int lr = tid >> 1;          // 0..127 tile row for loading
    const int kq = (tid & 1) * 4;     // 0 or 4

    const float* arow;
    {
        int m = m0 + lr;
        int t = m >> 5, b = m & 31;
        int tok = tokens[b * NL + t];
        arow = emb + (size_t)tok * 512;
    }
    const float* brow = W + (size_t)(n0 + lr) * 512;

    const int tm = (tid >> 4) * 8;
    const int tn = (tid & 15) * 8;

    unsigned long long acc2[8][4];    // 8 rows x 4 f32x2 pairs (8 cols)
#pragma unroll
    for (int i = 0; i < 8; i++)
#pragma unroll
        for (int p = 0; p < 4; p++) acc2[i][p] = 0ull;

    for (int k0 = 0; k0 < 512; k0 += 8) {
        float4 av = *(const float4*)(arow + k0 + kq);
        float4 bv = *(const float4*)(brow + k0 + kq);
        __syncthreads();
        As[kq + 0][lr] = av.x; As[kq + 1][lr] = av.y;
        As[kq + 2][lr] = av.z; As[kq + 3][lr] = av.w;
        Bs[kq + 0][lr] = bv.x; Bs[kq + 1][lr] = bv.y;
        Bs[kq + 2][lr] = bv.z; Bs[kq + 3][lr] = bv.w;
        __syncthreads();
#pragma unroll
        for (int kk = 0; kk < 8; kk++) {
            float a[8];
            *(float4*)(a)     = *(const float4*)(&As[kk][tm]);
            *(float4*)(a + 4) = *(const float4*)(&As[kk][tm + 4]);
            ulonglong2 b01 = *(const ulonglong2*)(&Bs[kk][tn]);
            ulonglong2 b23 = *(const ulonglong2*)(&Bs[kk][tn + 4]);
#pragma unroll
            for (int i = 0; i < 8; i++) {
                unsigned long long ad = pack2(a[i]);
                acc2[i][0] = ffma2(ad, b01.x, acc2[i][0]);
                acc2[i][1] = ffma2(ad, b01.y, acc2[i][1]);
                acc2[i][2] = ffma2(ad, b23.x, acc2[i][2]);
                acc2[i][3] = ffma2(ad, b23.y, acc2[i][3]);
            }
        }
    }

    ulonglong2 bi01 = *(const ulonglong2*)(&bias_s[tn]);
    ulonglong2 bi23 = *(const ulonglong2*)(&bias_s[tn + 4]);
#pragma unroll
    for (int i = 0; i < 8; i++) {
        float* orow = g_xg + (size_t)(m0 + tm + i) * NG + n0 + tn;
        ulonglong2 o0, o1;
        o0.x = addf2(acc2[i][0], bi01.x);
        o0.y = addf2(acc2[i][1], bi01.y);
        o1.x = addf2(acc2[i][2], bi23.x);
        o1.y = addf2(acc2[i][3], bi23.y);
        *(ulonglong2*)(orow)     = o0;
        *(ulonglong2*)(orow + 4) = o1;
    }
}

// ---------------------------------------------------------------------------
// Fused 2-layer pipelined LSTM recurrence. 128 CTAs x 256 threads.
// Fused step s (s = 0..512):
//   layer0 computes t=s      (active s<512): gA  = Whh0 @ h0[s-1]
//   layer1 computes t=s-1    (active s>=1) : gB  = Wih1 @ h0[s-1] + Whh1 @ h1[s-2]
// Both use previous-step state -> one merged k-loop, one grid barrier/step.
// Weights (3 slices of 16 gate rows) duplicated as (w,w) pairs in smem
// (FFMA2 operands). h read directly from global (L2); the barrier's
// ld.acquire.gpu invalidates L1 each step so plain LDG is coherent.
// ---------------------------------------------------------------------------
__global__ __launch_bounds__(256, 1) void lstm_fused(
    const float* __restrict__ Whh,     // (2, 2048, 512)
    const float* __restrict__ Wih,     // (2, 2048, 512)
    const float* __restrict__ bih,     // (2, 2048)
    const float* __restrict__ bhh,     // (2, 2048)
    float* __restrict__ d_out)
{
    extern __shared__ float sm[];
    float* w0   = sm;                    // 512*32 floats (Whh0 slice, dup pairs)
    float* w1i  = w0  + 512 * 32;        // 512*32       (Wih1 slice, dup pairs)
    float* w1h  = w1i + 512 * 32;        // 512*32       (Whh1 slice, dup pairs)
    float* redA = w1h + 512 * 32;        // 8*16*32 = 4096
    float* redB = redA + 4096;           // 4096
    float* c0_s = redB + 4096;           // 128
    float* c1_s = c0_s + 128;            // 128
    // total floats = 49152 + 8192 + 256 = 57600 -> 230400 B (< 227KB cap)

    const int tid = threadIdx.x;
    const int cta = blockIdx.x;          // 0..127 -> units [cta*4, cta*4+4)

    // One-time: load 3 weight slices (16 gate rows each), dup as (w,w) pairs
    for (int idx = tid; idx < 3 * 16 * 512; idx += 256) {
        int slice = idx >> 13;           // 0..2
        int rem   = idx & 8191;
        int lrw   = rem >> 9;            // 0..15 (q*4+u)
        int k     = rem & 511;
        int row   = (lrw >> 2) * 512 + cta * 4 + (lrw & 3);
        const float* src = (slice == 0) ? Whh
                         : (slice == 1) ? (Wih + (size_t)NG * NH)
                                        : (Whh + (size_t)NG * NH);
        float v = src[(size_t)row * 512 + k];
        float* dst = (slice == 0) ? w0 : (slice == 1) ? w1i : w1h;
        dst[k * 32 + lrw * 2]     = v;
        dst[k * 32 + lrw * 2 + 1] = v;
    }
    if (tid < 128) { c0_s[tid] = 0.f; c1_s[tid] = 0.f; }
    __syncthreads();

    const int lane = tid & 31, warp = tid >> 5;
    const int rg = lane >> 3, bg = lane & 7;
    const int k0 = warp * 64;

    // Gate-thread constants (tid < 128: u = warp 0..3, b = lane)
    const int uu = tid >> 5, bb = tid & 31;
    int   rowq[4];
    float b1[4];
    if (tid < 128) {
#pragma unroll
        for (int q = 0; q < 4; q++) {
            rowq[q] = q * 512 + cta * 4 + uu;
            b1[q] = bih[NG + rowq[q]] + bhh[NG + rowq[q]];
        }
    }

    const float* w0b  = w0  + rg * 8;
    const float* w1ib = w1i + rg * 8;
    const float* w1hb = w1h + rg * 8;

    for (int s = 0; s <= NL; s++) {
        // Prefetch layer-0 xg for this step (gate threads)
        float xg0[4];
        if (tid < 128) {
            int t0 = (s < NL) ? s : (NL - 1);
            const float* xp = g_xg + (size_t)(t0 * 32 + bb) * NG;
#pragma unroll
            for (int q = 0; q < 4; q++) xg0[q] = __ldg(xp + rowq[q]);
        }

        // h pointers (previous-step state; buffers alternate)
        const float* h0p = g_h0 + (s & 1) * (NH * NB) + bg * 4;
        const float* h1p = g_h1 + ((s & 1) ^ 1) * (NH * NB) + bg * 4;

        // Merged GEMM: A = Whh0@h0, B = Wih1@h0 + Whh1@h1 (warp owns K slice)
        unsigned long long A[8], Bv[8];
#pragma unroll
        for (int i = 0; i < 8; i++) { A[i] = 0ull; Bv[i] = 0ull; }

#pragma unroll 4
        for (int k = k0; k < k0 + 64; k++) {
            ulonglong2 H0 = *(const ulonglong2*)(h0p + k * 32);   // LDG (L2)
            ulonglong2 H1 = *(const ulonglong2*)(h1p + k * 32);   // LDG (L2)
            ulonglong2 Wa = *(const ulonglong2*)(w0b + k * 32);
            ulonglong2 Wb = *(const ulonglong2*)(w0b + k * 32 + 4);
            A[0] = ffma2(Wa.x, H0.x, A[0]); A[1] = ffma2(Wa.x, H0.y, A[1]);
            A[2] = ffma2(Wa.y, H0.x, A[2]); A[3] = ffma2(Wa.y, H0.y, A[3]);
            A[4] = ffma2(Wb.x, H0.x, A[4]); A[5] = ffma2(Wb.x, H0.y, A[5]);
            A[6] = ffma2(Wb.y, H0.x, A[6]); A[7] = ffma2(Wb.y, H0.y, A[7]);
            Wa = *(const ulonglong2*)(w1ib + k * 32);
            Wb = *(const ulonglong2*)(w1ib + k * 32 + 4);
            Bv[0] = ffma2(Wa.x, H0.x, Bv[0]); Bv[1] = ffma2(Wa.x, H0.y, Bv[1]);
            Bv[2] = ffma2(Wa.y, H0.x, Bv[2]); Bv[3] = ffma2(Wa.y, H0.y, Bv[3]);
            Bv[4] = ffma2(Wb.x, H0.x, Bv[4]); Bv[5] = ffma2(Wb.x, H0.y, Bv[5]);
            Bv[6] = ffma2(Wb.y, H0.x, Bv[6]); Bv[7] = ffma2(Wb.y, H0.y, Bv[7]);
            Wa = *(const ulonglong2*)(w1hb + k * 32);
            Wb = *(const ulonglong2*)(w1hb + k * 32 + 4);
            Bv[0] = ffma2(Wa.x, H1.x, Bv[0]); Bv[1] = ffma2(Wa.x, H1.y, Bv[1]);
            Bv[2] = ffma2(Wa.y, H1.x, Bv[2]); Bv[3] = ffma2(Wa.y, H1.y, Bv[3]);
            Bv[4] = ffma2(Wb.x, H1.x, Bv[4]); Bv[5] = ffma2(Wb.x, H1.y, Bv[5]);
            Bv[6] = ffma2(Wb.y, H1.x, Bv[6]); Bv[7] = ffma2(Wb.y, H1.y, Bv[7]);
        }

        // Store partials: row ri of this lane = warp*16 + rg*4 + ri
#pragma unroll
        for (int ri = 0; ri < 4; ri++) {
            float2 p, q;
            p = unpack2(A[2 * ri]); q = unpack2(A[2 * ri + 1]);
            *(float4*)(redA + ((warp * 16 + rg * 4 + ri) * 32 + bg * 4)) =
                make_float4(p.x, p.y, q.x, q.y);
            p = unpack2(Bv[2 * ri]); q = unpack2(Bv[2 * ri + 1]);
            *(float4*)(redB + ((warp * 16 + rg * 4 + ri) * 32 + bg * 4)) =
                make_float4(p.x, p.y, q.x, q.y);
        }
        __syncthreads();

        // Fused reduce + gates, both layers (tid < 128: one (u,b) each)
        if (tid < 128) {
            int j = cta * 4 + uu;
            if (s < NL) {   // layer 0, t = s
                float gq[4];
#pragma unroll
                for (int q = 0; q < 4; q++) {
                    float acc = xg0[q];
#pragma unroll
                    for (int w = 0; w < 8; w++)
                        acc += redA[(w * 16 + q * 4 + uu) * 32 + bb];
                    gq[q] = acc;
                }
                float ig = sigm_f(gq[0]);
                float fg = sigm_f(gq[1]);
                float cg = tanh_f(gq[2]);
                float og = sigm_f(gq[3]);
                float c = fg * c0_s[tid] + ig * cg;
                c0_s[tid] = c;
                float h = og * tanh_f(c);
                g_h0[((s + 1) & 1) * (NH * NB) + j * 32 + bb] = h;
                if (s == NL - 1) {
                    d_out[bb * NH + j] = h;                               // hidden L0
                    d_out[NLAYERS * NB * NH + bb * NH + j] = c;           // cell  L0
                }
            }
            if (s >= 1) {   // layer 1, t = s-1
                float gq[4];
#pragma unroll
                for (int q = 0; q < 4; q++) {
                    float acc = b1[q];
#pragma unroll
                    for (int w = 0; w < 8; w++)
                        acc += redB[(w * 16 + q * 4 + uu) * 32 + bb];
                    gq[q] = acc;
                }
                float ig = sigm_f(gq[0]);
                float fg = sigm_f(gq[1]);
                float cg = tanh_f(gq[2]);
                float og = sigm_f(gq[3]);
                float c = fg * c1_s[tid] + ig * cg;
                c1_s[tid] = c;
                float h = og * tanh_f(c);
                g_h1[(s & 1) * (NH * NB) + j * 32 + bb] = h;
                if (s == NL) {
                    d_out[NB * NH + bb * NH + j] = h;                     // hidden L1
                    d_out[NLAYERS * NB * NH + NB * NH + bb * NH + j] = c; // cell  L1
                }
            }
        }
        __syncthreads();

        // Grid-wide barrier (not needed after the last step)
        if (s < NL) {
            if (tid == 0) {
                __threadfence();
                atomicAdd(&g_bar, 1);
                int target = 128 * (s + 1);
                int v;
                do {
                    asm volatile("ld.acquire.gpu.s32 %0, [%1];"
                                 : "=r"(v) : "l"(&g_bar) : "memory");
                } while (v < target);
            }
            __syncthreads();
        }
    }
}

// ---------------------------------------------------------------------------
// Launcher
// ---------------------------------------------------------------------------
extern "C" void kernel_launch(void* const* d_in, const int* in_sizes, int n_in,
                              void* d_out, int out_size) {
    const int*   tokens = (const int*)  d_in[0];
    const float* emb    = (const float*)d_in[1];
    const float* Wih    = (const float*)d_in[2];   // (2, 2048, 512)
    const float* Whh    = (const float*)d_in[3];   // (2, 2048, 512)
    const float* bih    = (const float*)d_in[4];   // (2, 2048)
    const float* bhh    = (const float*)d_in[5];   // (2, 2048)
    float* out = (float*)d_out;

    const int FUSED_SMEM = (3 * 512 * 32 + 2 * 4096 + 256) * 4;   // 230400 B
    cudaFuncSetAttribute(lstm_fused, cudaFuncAttributeMaxDynamicSharedMemorySize,
                         FUSED_SMEM);

    dim3 ggrid(NG / 128, (NL * NB) / 128);   // (16, 128)

    // layer-0 input GEMM (embedding gather fused), then fused 2-layer recurrence
    xg_gemm<<<ggrid, 256>>>(emb, tokens, Wih, bih, bhh);
    init_kernel<<<1, 256>>>();
    lstm_fused<<<128, 256, FUSED_SMEM>>>(Whh, Wih, bih, bhh, out);
}

// round 12
// speedup vs baseline: 1.8421x; 1.4671x over previous
#include <cuda_runtime.h>
#include <cstdint>

// Problem constants
// B=32, L=512, E=H=512, G=4H=2048, N=2 layers, V=32000
#define NB 32
#define NL 512
#define NH 512
#define NG 2048
#define NLAYERS 2

// Scratch (static device globals -- allocation-free)
__device__ float g_xg[(size_t)NL * NB * NG];   // (L*B, 4H) layer-0 gate preacts (input part + bias)
__device__ float g_h0[2 * NH * NB];            // double-buffered h layer0, [buf][j][b]
__device__ float g_h1[2 * NH * NB];            // double-buffered h layer1, [buf][j][b]
__device__ int   g_bar;                        // global barrier counter

// ---------------------------------------------------------------------------
// Packed f32x2 helpers (fma.rn.f32x2 -- 2 fp32 MACs per instruction)
// ---------------------------------------------------------------------------
__device__ __forceinline__ unsigned long long ffma2(unsigned long long a,
                                                    unsigned long long b,
                                                    unsigned long long c) {
    unsigned long long d;
    asm("fma.rn.f32x2 %0, %1, %2, %3;" : "=l"(d) : "l"(a), "l"(b), "l"(c));
    return d;
}
__device__ __forceinline__ unsigned long long addf2(unsigned long long a,
                                                    unsigned long long b) {
    unsigned long long d;
    asm("add.rn.f32x2 %0, %1, %2;" : "=l"(d) : "l"(a), "l"(b));
    return d;
}
__device__ __forceinline__ unsigned long long pack2(float x) {
    unsigned long long d;
    asm("mov.b64 %0, {%1, %1};" : "=l"(d) : "f"(x));
    return d;
}
__device__ __forceinline__ float2 unpack2(unsigned long long u) {
    float2 f;
    asm("mov.b64 {%0, %1}, %2;" : "=f"(f.x), "=f"(f.y) : "l"(u));
    return f;
}

__device__ __forceinline__ float sigm_f(float x) {
    return 1.f / (1.f + __expf(-x));
}
// tanh via exp, precise division; clamp avoids inf/inf NaN. err ~1e-6 rel.
__device__ __forceinline__ float tanh_f(float x) {
    float xx = fminf(fmaxf(x, -15.f), 15.f);
    float e = __expf(2.f * xx);
    return (e - 1.f) / (e + 1.f);
}

// ---------------------------------------------------------------------------
// init: zero h states + barrier counter
// ---------------------------------------------------------------------------
__global__ void init_kernel() {
    int tid = threadIdx.x;
    for (int i = tid; i < 2 * NH * NB; i += 256) { g_h0[i] = 0.f; g_h1[i] = 0.f; }
    if (tid == 0) g_bar = 0;
}

// ---------------------------------------------------------------------------
// xg GEMM (layer 0 only): xg[m][n] = emb[tokens] @ Wih0^T + (bih0+bhh0)
// 128x128x8 tile, 256 threads, 8x8 microtile, FFMA2 inner product.
// ---------------------------------------------------------------------------
__global__ __launch_bounds__(256) void xg_gemm(
    const float* __restrict__ emb,
    const int*   __restrict__ tokens,
    const float* __restrict__ W,        // (2048, 512) row-major
    const float* __restrict__ bih_l,
    const float* __restrict__ bhh_l)
{
    __shared__ float As[8][128];
    __shared__ float Bs[8][128];
    __shared__ float bias_s[128];

    const int tid = threadIdx.x;
    const int n0 = blockIdx.x * 128;
    const int m0 = blockIdx.y * 128;

    if (tid < 128) bias_s[tid] = bih_l[n0 + tid] + bhh_l[n0 + tid];

    const int lr = tid >> 1;          // 0..127 tile row for loading
    const int kq = (tid & 1) * 4;     // 0 or 4

    const float* arow;
    {
        int m = m0 + lr;
        int t = m >> 5, b = m & 31;
        int tok = tokens[b * NL + t];
        arow = emb + (size_t)tok * 512;
    }
    const float* brow = W + (size_t)(n0 + lr) * 512;

    const int tm = (tid >> 4) * 8;
    const int tn = (tid & 15) * 8;

    unsigned long long acc2[8][4];    // 8 rows x 4 f32x2 pairs (8 cols)
#pragma unroll
    for (int i = 0; i < 8; i++)
#pragma unroll
        for (int p = 0; p < 4; p++) acc2[i][p] = 0ull;

    for (int k0 = 0; k0 < 512; k0 += 8) {
        float4 av = *(const float4*)(arow + k0 + kq);
        float4 bv = *(const float4*)(brow + k0 + kq);
        __syncthreads();
        As[kq + 0][lr] = av.x; As[kq + 1][lr] = av.y;
        As[kq + 2][lr] = av.z; As[kq + 3][lr] = av.w;
        Bs[kq + 0][lr] = bv.x; Bs[kq + 1][lr] = bv.y;
        Bs[kq + 2][lr] = bv.z; Bs[kq + 3][lr] = bv.w;
        __syncthreads();
#pragma unroll
        for (int kk = 0; kk < 8; kk++) {
            float a[8];
            *(float4*)(a)     = *(const float4*)(&As[kk][tm]);
            *(float4*)(a + 4) = *(const float4*)(&As[kk][tm + 4]);
            ulonglong2 b01 = *(const ulonglong2*)(&Bs[kk][tn]);
            ulonglong2 b23 = *(const ulonglong2*)(&Bs[kk][tn + 4]);
#pragma unroll
            for (int i = 0; i < 8; i++) {
                unsigned long long ad = pack2(a[i]);
                acc2[i][0] = ffma2(ad, b01.x, acc2[i][0]);
                acc2[i][1] = ffma2(ad, b01.y, acc2[i][1]);
                acc2[i][2] = ffma2(ad, b23.x, acc2[i][2]);
                acc2[i][3] = ffma2(ad, b23.y, acc2[i][3]);
            }
        }
    }

    ulonglong2 bi01 = *(const ulonglong2*)(&bias_s[tn]);
    ulonglong2 bi23 = *(const ulonglong2*)(&bias_s[tn + 4]);
#pragma unroll
    for (int i = 0; i < 8; i++) {
        float* orow = g_xg + (size_t)(m0 + tm + i) * NG + n0 + tn;
        ulonglong2 o0, o1;
        o0.x = addf2(acc2[i][0], bi01.x);
        o0.y = addf2(acc2[i][1], bi01.y);
        o1.x = addf2(acc2[i][2], bi23.x);
        o1.y = addf2(acc2[i][3], bi23.y);
        *(ulonglong2*)(orow)     = o0;
        *(ulonglong2*)(orow + 4) = o1;
    }
}

// ---------------------------------------------------------------------------
// Fused 2-layer pipelined LSTM recurrence. 128 CTAs x 512 threads (16 warps).
// Fused step s (s = 0..512):
//   layer0 computes t=s      (active s<512): gA = Whh0 @ h0[s-1]
//   layer1 computes t=s-1    (active s>=1) : gB = Wih1 @ h0[s-1] + Whh1 @ h1[s-2]
// K split 16 ways (32 k per warp). Weights NON-duplicated in smem; FFMA2 pairs
// over adjacent gate rows (weight pairs natural), h scalars dup'd via pack2
// (ALU pipe, hidden under fma). h read directly from global (L2, each element
// once per CTA per step); barrier's ld.acquire.gpu keeps it coherent.
// ---------------------------------------------------------------------------
#define REDSZ (16 * 16 * 33)   // [warp 0..15][row 0..15] stride-33 padded

__global__ __launch_bounds__(512, 1) void lstm_fused(
    const float* __restrict__ Whh,     // (2, 2048, 512)
    const float* __restrict__ Wih,     // (2, 2048, 512)
    const float* __restrict__ bih,     // (2, 2048)
    const float* __restrict__ bhh,     // (2, 2048)
    float* __restrict__ d_out)
{
    extern __shared__ float sm[];
    float* w0   = sm;                    // 512*16 floats (Whh0 slice, [k][row])
    float* w1i  = w0  + 512 * 16;        // 512*16       (Wih1 slice)
    float* w1h  = w1i + 512 * 16;        // 512*16       (Whh1 slice)
    float* redA = w1h + 512 * 16;        // REDSZ
    float* redB = redA + REDSZ;          // REDSZ
    float* c0_s = redB + REDSZ;          // 128
    float* c1_s = c0_s + 128;            // 128
    // total = 24576 + 2*8448 + 256 = 41728 floats = 166912 B

    const int tid = threadIdx.x;
    const int cta = blockIdx.x;          // 0..127 -> units [cta*4, cta*4+4)

    // One-time: load 3 weight slices (16 gate rows each), [k][row] layout
    for (int idx = tid; idx < 3 * 16 * 512; idx += 512) {
        int slice = idx >> 13;           // 0..2
        int rem   = idx & 8191;
        int lrw   = rem >> 9;            // 0..15 (q*4+u)
        int k     = rem & 511;
        int row   = (lrw >> 2) * 512 + cta * 4 + (lrw & 3);
        const float* src = (slice == 0) ? Whh
                         : (slice == 1) ? (Wih + (size_t)NG * NH)
                                        : (Whh + (size_t)NG * NH);
        float v = src[(size_t)row * 512 + k];
        float* dst = (slice == 0) ? w0 : (slice == 1) ? w1i : w1h;
        dst[k * 16 + lrw] = v;
    }
    if (tid < 128) { c0_s[tid] = 0.f; c1_s[tid] = 0.f; }
    __syncthreads();

    const int lane = tid & 31, warp = tid >> 5;   // warp 0..15
    const int rg = lane >> 3, bg = lane & 7;      // rg: 4 rows, bg: 4 batch
    const int k0 = warp * 32;                     // 32-k slice per warp

    // Gate-thread constants (tid < 256): set = tid>>7, u = (tid>>5)&3, b = tid&31
    const int gset = tid >> 7, uu = (tid >> 5) & 3, bb = tid & 31;
    int   rowq[4];
    float b1[4];
    if (tid < 256) {
#pragma unroll
        for (int q = 0; q < 4; q++) {
            rowq[q] = q * 512 + cta * 4 + uu;
            b1[q] = bih[NG + rowq[q]] + bhh[NG + rowq[q]];
        }
    }

    const float* w0b  = w0  + rg * 4;
    const float* w1ib = w1i + rg * 4;
    const float* w1hb = w1h + rg * 4;

    for (int s = 0; s <= NL; s++) {
        // Prefetch layer-0 xg for this step (set-A gate threads)
        float xg0[4];
        if (tid < 128) {
            int t0 = (s < NL) ? s : (NL - 1);
            const float* xp = g_xg + (size_t)(t0 * 32 + bb) * NG;
#pragma unroll
            for (int q = 0; q < 4; q++) xg0[q] = __ldg(xp + rowq[q]);
        }

        // h pointers (previous-step state; buffers alternate)
        const float* h0p = g_h0 + (s & 1) * (NH * NB) + bg * 4;
        const float* h1p = g_h1 + ((s & 1) ^ 1) * (NH * NB) + bg * 4;

        // Merged GEMM: A = Whh0@h0, B = Wih1@h0 + Whh1@h1.
        // Row-paired f32x2: accumulator X[rp*4+j] holds rows
        // (rg*4+rp*2, rg*4+rp*2+1) for batch bg*4+j.
        unsigned long long A[8], Bv[8];
#pragma unroll
        for (int i = 0; i < 8; i++) { A[i] = 0ull; Bv[i] = 0ull; }

#pragma unroll 8
        for (int k = k0; k < k0 + 32; k++) {
            float4 h0v = *(const float4*)(h0p + k * 32);   // LDG (L2)
            float4 h1v = *(const float4*)(h1p + k * 32);   // LDG (L2)
            unsigned long long d00 = pack2(h0v.x), d01 = pack2(h0v.y);
            unsigned long long d02 = pack2(h0v.z), d03 = pack2(h0v.w);
            unsigned long long d10 = pack2(h1v.x), d11 = pack2(h1v.y);
            unsigned long long d12 = pack2(h1v.z), d13 = pack2(h1v.w);

            ulonglong2 W0 = *(const ulonglong2*)(w0b + k * 16);
            A[0] = ffma2(W0.x, d00, A[0]); A[1] = ffma2(W0.x, d01, A[1]);
            A[2] = ffma2(W0.x, d02, A[2]); A[3] = ffma2(W0.x, d03, A[3]);
            A[4] = ffma2(W0.y, d00, A[4]); A[5] = ffma2(W0.y, d01, A[5]);
            A[6] = ffma2(W0.y, d02, A[6]); A[7] = ffma2(W0.y, d03, A[7]);

            ulonglong2 W1 = *(const ulonglong2*)(w1ib + k * 16);
            Bv[0] = ffma2(W1.x, d00, Bv[0]); Bv[1] = ffma2(W1.x, d01, Bv[1]);
            Bv[2] = ffma2(W1.x, d02, Bv[2]); Bv[3] = ffma2(W1.x, d03, Bv[3]);
            Bv[4] = ffma2(W1.y, d00, Bv[4]); Bv[5] = ffma2(W1.y, d01, Bv[5]);
            Bv[6] = ffma2(W1.y, d02, Bv[6]); Bv[7] = ffma2(W1.y, d03, Bv[7]);

            ulonglong2 W2 = *(const ulonglong2*)(w1hb + k * 16);
            Bv[0] = ffma2(W2.x, d10, Bv[0]); Bv[1] = ffma2(W2.x, d11, Bv[1]);
            Bv[2] = ffma2(W2.x, d12, Bv[2]); Bv[3] = ffma2(W2.x, d13, Bv[3]);
            Bv[4] = ffma2(W2.y, d10, Bv[4]); Bv[5] = ffma2(W2.y, d11, Bv[5]);
            Bv[6] = ffma2(W2.y, d12, Bv[6]); Bv[7] = ffma2(W2.y, d13, Bv[7]);
        }

        // Store partials: pair (p.x, p.y) = rows (rg*4+rp*2, +1), batch bg*4+j
#pragma unroll
        for (int rp = 0; rp < 2; rp++)
#pragma unroll
            for (int j = 0; j < 4; j++) {
                int b = bg * 4 + j;
                int r = rg * 4 + rp * 2;
                float2 p = unpack2(A[rp * 4 + j]);
                redA[(warp * 16 + r + 0) * 33 + b] = p.x;
                redA[(warp * 16 + r + 1) * 33 + b] = p.y;
                p = unpack2(Bv[rp * 4 + j]);
                redB[(warp * 16 + r + 0) * 33 + b] = p.x;
                redB[(warp * 16 + r + 1) * 33 + b] = p.y;
            }
        __syncthreads();

        // Fused reduce + gates (tid < 256: 2 warps/SMSP; set A: tid<128, set B: 128..255)
        if (tid < 256) {
            int j = cta * 4 + uu;
            if (gset == 0 && s < NL) {        // layer 0, t = s
                float gq[4];
#pragma unroll
                for (int q = 0; q < 4; q++) {
                    float acc = xg0[q];
                    const float* rp = redA + (q * 4 + uu) * 33 + bb;
#pragma unroll
                    for (int w = 0; w < 16; w++) acc += rp[w * 16 * 33];
                    gq[q] = acc;
                }
                float ig = sigm_f(gq[0]);
                float fg = sigm_f(gq[1]);
                float cg = tanh_f(gq[2]);
                float og = sigm_f(gq[3]);
                int ci = uu * 32 + bb;
                float c = fg * c0_s[ci] + ig * cg;
                c0_s[ci] = c;
                float h = og * tanh_f(c);
                g_h0[((s + 1) & 1) * (NH * NB) + j * 32 + bb] = h;
                if (s == NL - 1) {
                    d_out[bb * NH + j] = h;                               // hidden L0
                    d_out[NLAYERS * NB * NH + bb * NH + j] = c;           // cell  L0
                }
            }
            if (gset == 1 && s >= 1) {        // layer 1, t = s-1
                float gq[4];
#pragma unroll
                for (int q = 0; q < 4; q++) {
                    float acc = b1[q];
                    const float* rp = redB + (q * 4 + uu) * 33 + bb;
#pragma unroll
                    for (int w = 0; w < 16; w++) acc += rp[w * 16 * 33];
                    gq[q] = acc;
                }
                float ig = sigm_f(gq[0]);
                float fg = sigm_f(gq[1]);
                float cg = tanh_f(gq[2]);
                float og = sigm_f(gq[3]);
                int ci = uu * 32 + bb;
                float c = fg * c1_s[ci] + ig * cg;
                c1_s[ci] = c;
                float h = og * tanh_f(c);
                g_h1[(s & 1) * (NH * NB) + j * 32 + bb] = h;
                if (s == NL) {
                    d_out[NB * NH + bb * NH + j] = h;                     // hidden L1
                    d_out[NLAYERS * NB * NH + NB * NH + bb * NH + j] = c; // cell  L1
                }
            }
        }
        __syncthreads();

        // Grid-wide barrier (not needed after the last step)
        if (s < NL) {
            if (tid == 0) {
                __threadfence();
                atomicAdd(&g_bar, 1);
                int target = 128 * (s + 1);
                int v;
                do {
                    asm volatile("ld.acquire.gpu.s32 %0, [%1];"
                                 : "=r"(v) : "l"(&g_bar) : "memory");
                } while (v < target);
            }
            __syncthreads();
        }
    }
}

// ---------------------------------------------------------------------------
// Launcher
// ---------------------------------------------------------------------------
extern "C" void kernel_launch(void* const* d_in, const int* in_sizes, int n_in,
                              void* d_out, int out_size) {
    const int*   tokens = (const int*)  d_in[0];
    const float* emb    = (const float*)d_in[1];
    const float* Wih    = (const float*)d_in[2];   // (2, 2048, 512)
    const float* Whh    = (const float*)d_in[3];   // (2, 2048, 512)
    const float* bih    = (const float*)d_in[4];   // (2, 2048)
    const float* bhh    = (const float*)d_in[5];   // (2, 2048)
    float* out = (float*)d_out;

    const int FUSED_SMEM = (3 * 512 * 16 + 2 * REDSZ + 256) * 4;   // 166912 B
    cudaFuncSetAttribute(lstm_fused, cudaFuncAttributeMaxDynamicSharedMemorySize,
                         FUSED_SMEM);

    dim3 ggrid(NG / 128, (NL * NB) / 128);   // (16, 128)

    // layer-0 input GEMM (embedding gather fused), then fused 2-layer recurrence
    xg_gemm<<<ggrid, 256>>>(emb, tokens, Wih, bih, bhh);
    init_kernel<<<1, 256>>>();
    lstm_fused<<<128, 512, FUSED_SMEM>>>(Whh, Wih, bih, bhh, out);
}